// round 4
// baseline (speedup 1.0000x reference)
#include <cuda_runtime.h>
#include <cuda_fp16.h>
#include <math.h>

#define NMAX    100000
#define EMAX    1600000
#define NTYPES  17
#define DIM     128
#define GMAX    64
#define NBMAX   128
#define KSPLIT  4

// ---------------- static scratch ----------------
__device__ int   g_cnt[NMAX];
__device__ int   g_cur[NMAX];
__device__ int   g_rowptr[NMAX];   // local-exclusive; + g_bsums[i>>10] (scanned) on use
__device__ int   g_bsums[NBMAX];   // raw totals after scan1; scanned (exclusive) after k_mid
__device__ int   g_srcA[EMAX];
__device__ float g_dinv[NMAX];
__device__ int2  g_nd[NMAX];       // {dinv bits, node_type}
__device__ float g_htabp[KSPLIT * NTYPES * DIM];   // split-K partials of emb@W1
__device__ uint2 g_y1h[(size_t)NMAX * 32];          // fp16x4 per lane: y1s = dinv*relu(conv1)
__device__ float g_pool[GMAX * DIM];
__device__ int   g_gcnt[GMAX];

// ---------------- kernels ----------------

__global__ void k_init(int n) {
    int i = blockIdx.x * blockDim.x + threadIdx.x;
    if (i < n) g_cnt[i] = 0;
}

__global__ void k_hist(const int* __restrict__ ei, int E) {
    int e = blockIdx.x * blockDim.x + threadIdx.x;
    if (e < E) atomicAdd(&g_cnt[ei[E + e]], 1);
}

// per-block scan of counts; dinv + packed (dinv,type); zero g_cur
__global__ void k_scan1(const int* __restrict__ node_ids, int n) {
    __shared__ int s[1024];
    int t = threadIdx.x;
    int i = blockIdx.x * 1024 + t;
    int v = (i < n) ? g_cnt[i] : 0;
    if (i < n) {
        float dv = rsqrtf((float)(v + 1));
        g_dinv[i] = dv;
        g_nd[i] = make_int2(__float_as_int(dv), node_ids[i]);
        g_cur[i] = 0;
    }
    s[t] = v;
    __syncthreads();
    #pragma unroll
    for (int off = 1; off < 1024; off <<= 1) {
        int a = (t >= off) ? s[t - off] : 0;
        __syncthreads();
        s[t] += a;
        __syncthreads();
    }
    if (i < n) g_rowptr[i] = s[t] - v;
    if (t == 1023) g_bsums[blockIdx.x] = s[1023];
}

// block 0: exclusive scan of bsums; blocks 1..68: htab split-K partials;
// block 69: zero pool/gcnt
__global__ void __launch_bounds__(128) k_mid(int nb, const float* __restrict__ emb,
                                             const float* __restrict__ W1) {
    int b = blockIdx.x;
    if (b == 0) {
        __shared__ int s[NBMAX];
        int t = threadIdx.x;
        int v0 = (t < nb) ? g_bsums[t] : 0;
        int v1 = (t + 128 < nb) ? 0 : 0;   // NBMAX==128, 128 threads cover it
        (void)v1;
        s[t] = v0;
        __syncthreads();
        #pragma unroll
        for (int off = 1; off < NBMAX; off <<= 1) {
            int a = (t >= off) ? s[t - off] : 0;
            __syncthreads();
            s[t] += a;
            __syncthreads();
        }
        if (t < nb) g_bsums[t] = s[t] - v0;
    } else if (b <= KSPLIT * NTYPES) {
        int bb = b - 1;
        int t  = bb / KSPLIT;          // type row
        int ks = bb % KSPLIT;          // k-split
        int o  = threadIdx.x;          // output col
        int d0 = ks * (DIM / KSPLIT);
        float a0 = 0.f, a1 = 0.f, a2 = 0.f, a3 = 0.f;
        #pragma unroll
        for (int d = 0; d < DIM / KSPLIT; d += 4) {
            a0 = fmaf(emb[t * DIM + d0 + d + 0], W1[(d0 + d + 0) * DIM + o], a0);
            a1 = fmaf(emb[t * DIM + d0 + d + 1], W1[(d0 + d + 1) * DIM + o], a1);
            a2 = fmaf(emb[t * DIM + d0 + d + 2], W1[(d0 + d + 2) * DIM + o], a2);
            a3 = fmaf(emb[t * DIM + d0 + d + 3], W1[(d0 + d + 3) * DIM + o], a3);
        }
        g_htabp[ks * (NTYPES * DIM) + t * DIM + o] = (a0 + a1) + (a2 + a3);
    } else {
        // zero pool + gcnt
        int t = threadIdx.x;
        for (int i = t; i < GMAX * DIM; i += 128) g_pool[i] = 0.f;
        if (t < GMAX) g_gcnt[t] = 0;
    }
}

// CSR placement only
__global__ void k_scatter(const int* __restrict__ ei, int E) {
    int e = blockIdx.x * blockDim.x + threadIdx.x;
    if (e >= E) return;
    int s = ei[e];
    int d = ei[E + e];
    int p = atomicAdd(&g_cur[d], 1);
    g_srcA[g_rowptr[d] + g_bsums[d >> 10] + p] = s;
}

// Layer 1: per-node type coefficients built in-register from CSR in-edges
__global__ void __launch_bounds__(256) k_layer1(const float* __restrict__ b1, int n, int E) {
    __shared__ float4 sh[NTYPES * 32];   // summed htab partials, float4 rows
    __shared__ float4 sb[32];
    for (int i = threadIdx.x; i < NTYPES * 32; i += blockDim.x) {
        const float4* p = (const float4*)g_htabp;
        float4 a = p[i];
        float4 b = p[NTYPES * 32 + i];
        float4 c = p[2 * NTYPES * 32 + i];
        float4 d = p[3 * NTYPES * 32 + i];
        float4 r;
        r.x = (a.x + b.x) + (c.x + d.x);
        r.y = (a.y + b.y) + (c.y + d.y);
        r.z = (a.z + b.z) + (c.z + d.z);
        r.w = (a.w + b.w) + (c.w + d.w);
        sh[i] = r;
    }
    if (threadIdx.x < 32) sb[threadIdx.x] = ((const float4*)b1)[threadIdx.x];
    __syncthreads();

    int warp = threadIdx.x >> 5, lane = threadIdx.x & 31;
    int i = blockIdx.x * 8 + warp;
    if (i >= n) return;

    int2 nd = g_nd[i];
    float di = __int_as_float(nd.x);
    int ti = nd.y;

    int e0 = g_rowptr[i] + g_bsums[i >> 10];
    int e1 = (i + 1 < n) ? (g_rowptr[i + 1] + g_bsums[(i + 1) >> 10]) : E;

    // per-lane type coefficient (lane l owns type l for l < NTYPES)
    float c = 0.f;
    for (int e = e0; e < e1; e += 32) {
        int idx = e + lane;
        bool v = idx < e1;
        int s = v ? g_srcA[idx] : 0;
        int2 snd = v ? __ldg(&g_nd[s]) : make_int2(0, 0);
        float w = v ? __int_as_float(snd.x) : 0.f;
        int ty = snd.y;
        #pragma unroll
        for (int r = 0; r < 32; r++) {
            float bw = __shfl_sync(0xffffffffu, w, r);
            int   bt = __shfl_sync(0xffffffffu, ty, r);
            c += (bt == lane) ? bw : 0.f;
        }
    }

    float4 acc = {0.f, 0.f, 0.f, 0.f};
    #pragma unroll
    for (int t = 0; t < NTYPES; t++) {
        float ct = __shfl_sync(0xffffffffu, c, t);
        if (t == ti) ct += di;                   // self-loop
        float4 h = sh[t * 32 + lane];
        acc.x = fmaf(ct, h.x, acc.x);
        acc.y = fmaf(ct, h.y, acc.y);
        acc.z = fmaf(ct, h.z, acc.z);
        acc.w = fmaf(ct, h.w, acc.w);
    }
    float4 bb = sb[lane];
    float4 r;
    r.x = di * fmaxf(fmaf(di, acc.x, bb.x), 0.f);
    r.y = di * fmaxf(fmaf(di, acc.y, bb.y), 0.f);
    r.z = di * fmaxf(fmaf(di, acc.z, bb.z), 0.f);
    r.w = di * fmaxf(fmaf(di, acc.w, bb.w), 0.f);
    __half2 p0 = __floats2half2_rn(r.x, r.y);
    __half2 p1 = __floats2half2_rn(r.z, r.w);
    uint2 u;
    u.x = *(unsigned int*)&p0;
    u.y = *(unsigned int*)&p1;
    g_y1h[(size_t)i * 32 + lane] = u;
}

__device__ __forceinline__ void acc_row(float4& acc, uint2 u) {
    float2 f0 = __half22float2(*(__half2*)&u.x);
    float2 f1 = __half22float2(*(__half2*)&u.y);
    acc.x += f0.x; acc.y += f0.y; acc.z += f1.x; acc.w += f1.y;
}

// Layer 2 aggregation (fp16 gather-sum, fp32 accum) fused with graph pooling
__global__ void __launch_bounds__(256) k_layer2pool(const int* __restrict__ batch, int n, int E) {
    __shared__ float sy[8 * DIM];
    __shared__ int sg[8];

    int warp = threadIdx.x >> 5, lane = threadIdx.x & 31;
    int i = blockIdx.x * 8 + warp;

    if (i < n) {
        const uint2* y = (const uint2*)g_y1h;
        float di = g_dinv[i];
        float4 acc = {0.f, 0.f, 0.f, 0.f};
        acc_row(acc, __ldg(&y[(size_t)i * 32 + lane]));   // self loop

        int e  = g_rowptr[i] + g_bsums[i >> 10];
        int e1 = (i + 1 < n) ? (g_rowptr[i + 1] + g_bsums[(i + 1) >> 10]) : E;

        for (; e + 8 <= e1; e += 8) {
            uint2 u0 = __ldg(&y[(size_t)g_srcA[e + 0] * 32 + lane]);
            uint2 u1 = __ldg(&y[(size_t)g_srcA[e + 1] * 32 + lane]);
            uint2 u2 = __ldg(&y[(size_t)g_srcA[e + 2] * 32 + lane]);
            uint2 u3 = __ldg(&y[(size_t)g_srcA[e + 3] * 32 + lane]);
            uint2 u4 = __ldg(&y[(size_t)g_srcA[e + 4] * 32 + lane]);
            uint2 u5 = __ldg(&y[(size_t)g_srcA[e + 5] * 32 + lane]);
            uint2 u6 = __ldg(&y[(size_t)g_srcA[e + 6] * 32 + lane]);
            uint2 u7 = __ldg(&y[(size_t)g_srcA[e + 7] * 32 + lane]);
            acc_row(acc, u0); acc_row(acc, u1); acc_row(acc, u2); acc_row(acc, u3);
            acc_row(acc, u4); acc_row(acc, u5); acc_row(acc, u6); acc_row(acc, u7);
        }
        for (; e < e1; e++)
            acc_row(acc, __ldg(&y[(size_t)g_srcA[e] * 32 + lane]));

        acc.x *= di; acc.y *= di; acc.z *= di; acc.w *= di;
        ((float4*)sy)[warp * 32 + lane] = acc;
        if (lane == 0) sg[warp] = batch[i];
    } else {
        if (lane == 0) sg[warp] = -1;
    }
    __syncthreads();

    int f = threadIdx.x;
    if (f < DIM) {
        float run = 0.f; int cg = -1; int cnt = 0;
        #pragma unroll
        for (int r = 0; r < 8; r++) {
            int g = sg[r];
            if (g < 0) continue;
            if (g != cg) {
                if (cg >= 0) {
                    atomicAdd(&g_pool[cg * DIM + f], run);
                    if (f == 0) atomicAdd(&g_gcnt[cg], cnt);
                }
                cg = g; run = 0.f; cnt = 0;
            }
            run += sy[r * DIM + f];
            cnt++;
        }
        if (cg >= 0) {
            atomicAdd(&g_pool[cg * DIM + f], run);
            if (f == 0) atomicAdd(&g_gcnt[cg], cnt);
        }
    }
}

// out[g] = (pool[g]/cnt[g]) @ W2 + b2
__global__ void k_final(const float* __restrict__ W2, const float* __restrict__ b2,
                        float* __restrict__ out) {
    int g = blockIdx.x, o = threadIdx.x;
    __shared__ float p[DIM];
    int c = g_gcnt[g];
    float inv = (c > 0) ? (1.0f / (float)c) : 0.f;
    p[o] = g_pool[g * DIM + o] * inv;
    __syncthreads();
    float a0 = 0.f, a1 = 0.f, a2 = 0.f, a3 = 0.f;
    #pragma unroll
    for (int d = 0; d < DIM; d += 4) {
        a0 = fmaf(p[d + 0], W2[(d + 0) * DIM + o], a0);
        a1 = fmaf(p[d + 1], W2[(d + 1) * DIM + o], a1);
        a2 = fmaf(p[d + 2], W2[(d + 2) * DIM + o], a2);
        a3 = fmaf(p[d + 3], W2[(d + 3) * DIM + o], a3);
    }
    out[g * DIM + o] = (c > 0) ? ((a0 + a1) + (a2 + a3) + b2[o]) : 0.f;
}

// ---------------- launcher ----------------
extern "C" void kernel_launch(void* const* d_in, const int* in_sizes, int n_in,
                              void* d_out, int out_size) {
    const int* node_ids = (const int*)d_in[0];
    const int* ei       = (const int*)d_in[1];
    const int* batch    = (const int*)d_in[2];
    int base = (n_in >= 9 && in_sizes[3] == 1) ? 4 : 3;
    const float* emb = (const float*)d_in[base + 0];
    const float* W1  = (const float*)d_in[base + 1];
    const float* b1  = (const float*)d_in[base + 2];
    const float* W2  = (const float*)d_in[base + 3];
    const float* b2  = (const float*)d_in[base + 4];

    int N = in_sizes[0];
    int E = in_sizes[1] / 2;
    int G = out_size / DIM;
    int NB = (N + 1023) / 1024;

    k_init<<<(N + 255) / 256, 256>>>(N);
    k_hist<<<(E + 255) / 256, 256>>>(ei, E);
    k_scan1<<<NB, 1024>>>(node_ids, N);
    k_mid<<<KSPLIT * NTYPES + 2, 128>>>(NB, emb, W1);
    k_scatter<<<(E + 255) / 256, 256>>>(ei, E);
    k_layer1<<<(N + 7) / 8, 256>>>(b1, N, E);
    k_layer2pool<<<(N + 7) / 8, 256>>>(batch, N, E);
    k_final<<<G, DIM>>>(W2, b2, (float*)d_out);
}

// round 5
// speedup vs baseline: 1.2259x; 1.2259x over previous
#include <cuda_runtime.h>
#include <cuda_fp16.h>
#include <math.h>

#define NMAX    100000
#define EMAX    1600000
#define NTYPES  17
#define DIM     128
#define GMAX    64
#define NBMAX   128
#define HTB     9      // htab helper blocks inside k_hist

// ---------------- static scratch (all zero-init; self-restoring across replays) ----------------
__device__ int   g_cnt[NMAX];      // hist fills; scatter drains back to 0
__device__ int   g_rowptr[NMAX];   // local-exclusive; + g_bsums[i>>10] on use
__device__ int   g_bsums[NBMAX];
__device__ int   g_sctr;           // scan election counter (self-resets)
__device__ unsigned g_ndp[NMAX];   // (dinv bits & ~31) | type
__device__ int2  g_edge[EMAX];     // {src, (dinv_src bits & ~31) | type_src}
__device__ float g_htab[NTYPES * DIM];
__device__ uint2 g_y1h[(size_t)NMAX * 32];   // fp16x4/lane: y1s = dinv*relu(conv1)
__device__ float g_pool[GMAX * DIM];         // k_final re-zeros
__device__ int   g_gcnt[GMAX];               // k_final re-zeros

// ---------------- kernels ----------------

// blocks 0..HTB-1: htab = emb @ W1 ; rest: in-degree histogram
__global__ void __launch_bounds__(256) k_hist(const int* __restrict__ ei, int E,
                                              const float* __restrict__ emb,
                                              const float* __restrict__ W1) {
    int b = blockIdx.x;
    if (b < HTB) {
        int idx = b * 256 + threadIdx.x;
        if (idx < NTYPES * DIM) {
            int t = idx / DIM, o = idx % DIM;
            float a0 = 0.f, a1 = 0.f, a2 = 0.f, a3 = 0.f;
            #pragma unroll
            for (int d = 0; d < DIM; d += 4) {
                a0 = fmaf(emb[t * DIM + d + 0], W1[(d + 0) * DIM + o], a0);
                a1 = fmaf(emb[t * DIM + d + 1], W1[(d + 1) * DIM + o], a1);
                a2 = fmaf(emb[t * DIM + d + 2], W1[(d + 2) * DIM + o], a2);
                a3 = fmaf(emb[t * DIM + d + 3], W1[(d + 3) * DIM + o], a3);
            }
            g_htab[idx] = (a0 + a1) + (a2 + a3);
        }
        return;
    }
    int e = (b - HTB) * 256 + threadIdx.x;
    if (e < E) atomicAdd(&g_cnt[ei[E + e]], 1);
}

// per-block scan of counts; ndp pack; elected last block scans bsums
__global__ void k_scan1(const int* __restrict__ node_ids, int n) {
    __shared__ int s[1024];
    __shared__ int s_elect;
    int t = threadIdx.x;
    int i = blockIdx.x * 1024 + t;
    int v = (i < n) ? g_cnt[i] : 0;
    if (i < n) {
        float dv = rsqrtf((float)(v + 1));
        g_ndp[i] = (__float_as_uint(dv) & ~31u) | (unsigned)node_ids[i];
    }
    s[t] = v;
    __syncthreads();
    #pragma unroll
    for (int off = 1; off < 1024; off <<= 1) {
        int a = (t >= off) ? s[t - off] : 0;
        __syncthreads();
        s[t] += a;
        __syncthreads();
    }
    if (i < n) g_rowptr[i] = s[t] - v;
    if (t == 1023) g_bsums[blockIdx.x] = s[1023];
    __syncthreads();

    if (t == 0) {
        __threadfence();
        int old = atomicAdd(&g_sctr, 1);
        s_elect = (old == (int)gridDim.x - 1);
    }
    __syncthreads();
    if (s_elect) {
        int nb = gridDim.x;
        int v0 = 0;
        if (t < NBMAX) { v0 = (t < nb) ? g_bsums[t] : 0; s[t] = v0; }
        __syncthreads();
        #pragma unroll
        for (int off = 1; off < NBMAX; off <<= 1) {
            int a = 0;
            if (t < NBMAX && t >= off) a = s[t - off];
            __syncthreads();
            if (t < NBMAX) s[t] += a;
            __syncthreads();
        }
        if (t < nb) g_bsums[t] = s[t] - v0;      // exclusive block offsets
        if (t == 0) g_sctr = 0;                  // self-reset for next replay
    }
}

// CSR placement; g_cnt doubles as cursor (drains to 0)
__global__ void k_scatter(const int* __restrict__ ei, int E) {
    int e = blockIdx.x * blockDim.x + threadIdx.x;
    if (e >= E) return;
    int s = ei[e];
    int d = ei[E + e];
    int p = atomicAdd(&g_cnt[d], -1) - 1;
    g_edge[g_rowptr[d] + g_bsums[d >> 10] + p] = make_int2(s, (int)__ldg(&g_ndp[s]));
}

// Layer 1: per-warp smem type-coefficient accumulation + 17-type FMA
__global__ void __launch_bounds__(256) k_layer1(const float* __restrict__ b1, int n, int E) {
    __shared__ float4 sh[NTYPES * 32];
    __shared__ float4 sb[32];
    __shared__ float warpc[8][32];
    for (int i = threadIdx.x; i < NTYPES * 32; i += blockDim.x)
        sh[i] = ((const float4*)g_htab)[i];
    if (threadIdx.x < 32) sb[threadIdx.x] = ((const float4*)b1)[threadIdx.x];
    __syncthreads();

    int warp = threadIdx.x >> 5, lane = threadIdx.x & 31;
    int i = blockIdx.x * 8 + warp;
    if (i >= n) return;

    warpc[warp][lane] = 0.f;
    __syncwarp();

    unsigned pki = g_ndp[i];
    float di = __uint_as_float(pki & ~31u);
    int ti = (int)(pki & 31u);

    int e0 = g_rowptr[i] + g_bsums[i >> 10];
    int e1 = (i + 1 < n) ? (g_rowptr[i + 1] + g_bsums[(i + 1) >> 10]) : E;

    for (int e = e0; e < e1; e += 32) {
        int idx = e + lane;
        if (idx < e1) {
            unsigned pk = (unsigned)g_edge[idx].y;
            atomicAdd(&warpc[warp][pk & 31u], __uint_as_float(pk & ~31u));
        }
    }
    __syncwarp();

    float4 acc = {0.f, 0.f, 0.f, 0.f};
    #pragma unroll
    for (int t = 0; t < NTYPES; t++) {
        float ct = warpc[warp][t];
        if (t == ti) ct += di;                 // self-loop
        float4 h = sh[t * 32 + lane];
        acc.x = fmaf(ct, h.x, acc.x);
        acc.y = fmaf(ct, h.y, acc.y);
        acc.z = fmaf(ct, h.z, acc.z);
        acc.w = fmaf(ct, h.w, acc.w);
    }
    float4 bb = sb[lane];
    float4 r;
    r.x = di * fmaxf(fmaf(di, acc.x, bb.x), 0.f);
    r.y = di * fmaxf(fmaf(di, acc.y, bb.y), 0.f);
    r.z = di * fmaxf(fmaf(di, acc.z, bb.z), 0.f);
    r.w = di * fmaxf(fmaf(di, acc.w, bb.w), 0.f);
    __half2 p0 = __floats2half2_rn(r.x, r.y);
    __half2 p1 = __floats2half2_rn(r.z, r.w);
    uint2 u;
    u.x = *(unsigned int*)&p0;
    u.y = *(unsigned int*)&p1;
    g_y1h[(size_t)i * 32 + lane] = u;
}

__device__ __forceinline__ void acc_row(float4& acc, uint2 u) {
    float2 f0 = __half22float2(*(__half2*)&u.x);
    float2 f1 = __half22float2(*(__half2*)&u.y);
    acc.x += f0.x; acc.y += f0.y; acc.z += f1.x; acc.w += f1.y;
}

// Layer 2 aggregation (fp16 gather, fp32 accum) fused with graph pooling
__global__ void __launch_bounds__(256) k_layer2pool(const int* __restrict__ batch, int n, int E) {
    __shared__ float sy[8 * DIM];
    __shared__ int sg[8];

    int warp = threadIdx.x >> 5, lane = threadIdx.x & 31;
    int i = blockIdx.x * 8 + warp;

    if (i < n) {
        const uint2* y = (const uint2*)g_y1h;
        float di = __uint_as_float(g_ndp[i] & ~31u);
        float4 acc = {0.f, 0.f, 0.f, 0.f};
        acc_row(acc, __ldg(&y[(size_t)i * 32 + lane]));   // self loop

        int e  = g_rowptr[i] + g_bsums[i >> 10];
        int e1 = (i + 1 < n) ? (g_rowptr[i + 1] + g_bsums[(i + 1) >> 10]) : E;

        for (; e + 8 <= e1; e += 8) {
            int s0 = g_edge[e + 0].x, s1 = g_edge[e + 1].x;
            int s2 = g_edge[e + 2].x, s3 = g_edge[e + 3].x;
            int s4 = g_edge[e + 4].x, s5 = g_edge[e + 5].x;
            int s6 = g_edge[e + 6].x, s7 = g_edge[e + 7].x;
            uint2 u0 = __ldg(&y[(size_t)s0 * 32 + lane]);
            uint2 u1 = __ldg(&y[(size_t)s1 * 32 + lane]);
            uint2 u2 = __ldg(&y[(size_t)s2 * 32 + lane]);
            uint2 u3 = __ldg(&y[(size_t)s3 * 32 + lane]);
            uint2 u4 = __ldg(&y[(size_t)s4 * 32 + lane]);
            uint2 u5 = __ldg(&y[(size_t)s5 * 32 + lane]);
            uint2 u6 = __ldg(&y[(size_t)s6 * 32 + lane]);
            uint2 u7 = __ldg(&y[(size_t)s7 * 32 + lane]);
            acc_row(acc, u0); acc_row(acc, u1); acc_row(acc, u2); acc_row(acc, u3);
            acc_row(acc, u4); acc_row(acc, u5); acc_row(acc, u6); acc_row(acc, u7);
        }
        for (; e < e1; e++)
            acc_row(acc, __ldg(&y[(size_t)g_edge[e].x * 32 + lane]));

        acc.x *= di; acc.y *= di; acc.z *= di; acc.w *= di;
        ((float4*)sy)[warp * 32 + lane] = acc;
        if (lane == 0) sg[warp] = batch[i];
    } else {
        if (lane == 0) sg[warp] = -1;
    }
    __syncthreads();

    int f = threadIdx.x;
    if (f < DIM) {
        float run = 0.f; int cg = -1; int cnt = 0;
        #pragma unroll
        for (int r = 0; r < 8; r++) {
            int g = sg[r];
            if (g < 0) continue;
            if (g != cg) {
                if (cg >= 0) {
                    atomicAdd(&g_pool[cg * DIM + f], run);
                    if (f == 0) atomicAdd(&g_gcnt[cg], cnt);
                }
                cg = g; run = 0.f; cnt = 0;
            }
            run += sy[r * DIM + f];
            cnt++;
        }
        if (cg >= 0) {
            atomicAdd(&g_pool[cg * DIM + f], run);
            if (f == 0) atomicAdd(&g_gcnt[cg], cnt);
        }
    }
}

// out[g] = (pool[g]/cnt[g]) @ W2 + b2 ; re-zeros pool/gcnt for next replay
__global__ void k_final(const float* __restrict__ W2, const float* __restrict__ b2,
                        float* __restrict__ out) {
    int g = blockIdx.x, o = threadIdx.x;
    __shared__ float p[DIM];
    int c = g_gcnt[g];
    float inv = (c > 0) ? (1.0f / (float)c) : 0.f;
    p[o] = g_pool[g * DIM + o] * inv;
    g_pool[g * DIM + o] = 0.f;
    if (o == 0) g_gcnt[g] = 0;
    __syncthreads();
    float a0 = 0.f, a1 = 0.f, a2 = 0.f, a3 = 0.f;
    #pragma unroll
    for (int d = 0; d < DIM; d += 4) {
        a0 = fmaf(p[d + 0], W2[(d + 0) * DIM + o], a0);
        a1 = fmaf(p[d + 1], W2[(d + 1) * DIM + o], a1);
        a2 = fmaf(p[d + 2], W2[(d + 2) * DIM + o], a2);
        a3 = fmaf(p[d + 3], W2[(d + 3) * DIM + o], a3);
    }
    out[g * DIM + o] = (c > 0) ? ((a0 + a1) + (a2 + a3) + b2[o]) : 0.f;
}

// ---------------- launcher ----------------
extern "C" void kernel_launch(void* const* d_in, const int* in_sizes, int n_in,
                              void* d_out, int out_size) {
    const int* node_ids = (const int*)d_in[0];
    const int* ei       = (const int*)d_in[1];
    const int* batch    = (const int*)d_in[2];
    int base = (n_in >= 9 && in_sizes[3] == 1) ? 4 : 3;
    const float* emb = (const float*)d_in[base + 0];
    const float* W1  = (const float*)d_in[base + 1];
    const float* b1  = (const float*)d_in[base + 2];
    const float* W2  = (const float*)d_in[base + 3];
    const float* b2  = (const float*)d_in[base + 4];

    int N = in_sizes[0];
    int E = in_sizes[1] / 2;
    int G = out_size / DIM;
    int NB = (N + 1023) / 1024;

    k_hist<<<HTB + (E + 255) / 256, 256>>>(ei, E, emb, W1);
    k_scan1<<<NB, 1024>>>(node_ids, N);
    k_scatter<<<(E + 255) / 256, 256>>>(ei, E);
    k_layer1<<<(N + 7) / 8, 256>>>(b1, N, E);
    k_layer2pool<<<(N + 7) / 8, 256>>>(batch, N, E);
    k_final<<<G, DIM>>>(W2, b2, (float*)d_out);
}

// round 6
// speedup vs baseline: 1.3497x; 1.1010x over previous
#include <cuda_runtime.h>
#include <cuda_fp16.h>
#include <math.h>

#define NMAX    100000
#define EMAX    1600000
#define NTYPES  17
#define DIM     128
#define GMAX    64
#define NBMAX   128
#define HTB     9      // htab helper blocks inside k_hist

// ---------------- static scratch (all zero-init; self-restoring across replays) ----------------
__device__ int   g_cnt[NMAX];      // hist fills; scatter drains back to 0
__device__ int   g_rowptr[NMAX];   // local-exclusive; + g_bsums[i>>10] on use
__device__ int   g_bsums[NBMAX];
__device__ int   g_sctr;           // scan election counter (self-resets)
__device__ unsigned g_ndp[NMAX];   // (dinv bits & ~31) | type
__device__ int2  g_edge[EMAX];     // {src, (dinv_src bits & ~31) | type_src}
__device__ float g_htab[NTYPES * DIM];
__device__ uint2 g_y1h[(size_t)NMAX * 32];   // fp16x4/lane: y1s = dinv*relu(conv1)
__device__ float g_pool[GMAX * DIM];         // k_final re-zeros
__device__ int   g_gcnt[GMAX];               // k_final re-zeros

// ---------------- kernels ----------------

// blocks 0..HTB-1: htab = emb @ W1 ; rest: in-degree histogram
__global__ void __launch_bounds__(256) k_hist(const int* __restrict__ ei, int E,
                                              const float* __restrict__ emb,
                                              const float* __restrict__ W1) {
    int b = blockIdx.x;
    if (b < HTB) {
        int idx = b * 256 + threadIdx.x;
        if (idx < NTYPES * DIM) {
            int t = idx / DIM, o = idx % DIM;
            float a0 = 0.f, a1 = 0.f, a2 = 0.f, a3 = 0.f;
            #pragma unroll
            for (int d = 0; d < DIM; d += 4) {
                a0 = fmaf(emb[t * DIM + d + 0], W1[(d + 0) * DIM + o], a0);
                a1 = fmaf(emb[t * DIM + d + 1], W1[(d + 1) * DIM + o], a1);
                a2 = fmaf(emb[t * DIM + d + 2], W1[(d + 2) * DIM + o], a2);
                a3 = fmaf(emb[t * DIM + d + 3], W1[(d + 3) * DIM + o], a3);
            }
            g_htab[idx] = (a0 + a1) + (a2 + a3);
        }
        return;
    }
    int e = (b - HTB) * 256 + threadIdx.x;
    if (e < E) atomicAdd(&g_cnt[ei[E + e]], 1);
}

// per-block scan of counts; ndp pack; elected last block scans bsums
__global__ void k_scan1(const int* __restrict__ node_ids, int n) {
    __shared__ int s[1024];
    __shared__ int s_elect;
    int t = threadIdx.x;
    int i = blockIdx.x * 1024 + t;
    int v = (i < n) ? g_cnt[i] : 0;
    if (i < n) {
        float dv = rsqrtf((float)(v + 1));
        g_ndp[i] = (__float_as_uint(dv) & ~31u) | (unsigned)node_ids[i];
    }
    s[t] = v;
    __syncthreads();
    #pragma unroll
    for (int off = 1; off < 1024; off <<= 1) {
        int a = (t >= off) ? s[t - off] : 0;
        __syncthreads();
        s[t] += a;
        __syncthreads();
    }
    if (i < n) g_rowptr[i] = s[t] - v;
    if (t == 1023) g_bsums[blockIdx.x] = s[1023];
    __syncthreads();

    if (t == 0) {
        __threadfence();
        int old = atomicAdd(&g_sctr, 1);
        s_elect = (old == (int)gridDim.x - 1);
    }
    __syncthreads();
    if (s_elect) {
        int nb = gridDim.x;
        int v0 = 0;
        if (t < NBMAX) { v0 = (t < nb) ? g_bsums[t] : 0; s[t] = v0; }
        __syncthreads();
        #pragma unroll
        for (int off = 1; off < NBMAX; off <<= 1) {
            int a = 0;
            if (t < NBMAX && t >= off) a = s[t - off];
            __syncthreads();
            if (t < NBMAX) s[t] += a;
            __syncthreads();
        }
        if (t < nb) g_bsums[t] = s[t] - v0;      // exclusive block offsets
        if (t == 0) g_sctr = 0;                  // self-reset for next replay
    }
}

// CSR placement; g_cnt doubles as cursor (drains to 0)
__global__ void k_scatter(const int* __restrict__ ei, int E) {
    int e = blockIdx.x * blockDim.x + threadIdx.x;
    if (e >= E) return;
    int s = ei[e];
    int d = ei[E + e];
    int p = atomicAdd(&g_cnt[d], -1) - 1;
    g_edge[g_rowptr[d] + g_bsums[d >> 10] + p] = make_int2(s, (int)__ldg(&g_ndp[s]));
}

// Layer 1: 4 nodes per warp; smem type-coefficient rows; htab LDS amortized 4x
__global__ void __launch_bounds__(256) k_layer1(const float* __restrict__ b1, int n, int E) {
    __shared__ float4 sh[NTYPES * 32];
    __shared__ float4 sb[32];
    __shared__ float warpc[8][4][32];
    for (int i = threadIdx.x; i < NTYPES * 32; i += blockDim.x)
        sh[i] = ((const float4*)g_htab)[i];
    if (threadIdx.x < 32) sb[threadIdx.x] = ((const float4*)b1)[threadIdx.x];
    __syncthreads();

    int warp = threadIdx.x >> 5, lane = threadIdx.x & 31;
    int ibase = (blockIdx.x * 8 + warp) * 4;
    if (ibase >= n) return;

    // zero the 4 coefficient rows
    #pragma unroll
    for (int j = 0; j < 4; j++) warpc[warp][j][lane] = 0.f;
    __syncwarp();

    // lane j (<4) pre-folds its node's self-loop dinv into its type slot
    unsigned mypk = 0;
    if (lane < 4 && ibase + lane < n) {
        mypk = g_ndp[ibase + lane];
        atomicAdd(&warpc[warp][lane][mypk & 31u], __uint_as_float(mypk & ~31u));
    }

    // per-node edge coefficient accumulation
    #pragma unroll
    for (int j = 0; j < 4; j++) {
        int i = ibase + j;
        if (i >= n) break;
        int e0 = g_rowptr[i] + g_bsums[i >> 10];
        int e1 = (i + 1 < n) ? (g_rowptr[i + 1] + g_bsums[(i + 1) >> 10]) : E;
        for (int e = e0 + lane; e < e1; e += 32) {
            unsigned pk = (unsigned)g_edge[e].y;
            atomicAdd(&warpc[warp][j][pk & 31u], __uint_as_float(pk & ~31u));
        }
    }
    __syncwarp();

    // 17-type FMA: one LDS.128 of h serves 4 nodes
    float4 a0 = {0.f,0.f,0.f,0.f}, a1 = {0.f,0.f,0.f,0.f};
    float4 a2 = {0.f,0.f,0.f,0.f}, a3 = {0.f,0.f,0.f,0.f};
    #pragma unroll
    for (int t = 0; t < NTYPES; t++) {
        float4 h = sh[t * 32 + lane];
        float c0 = warpc[warp][0][t];
        float c1 = warpc[warp][1][t];
        float c2 = warpc[warp][2][t];
        float c3 = warpc[warp][3][t];
        a0.x = fmaf(c0, h.x, a0.x); a0.y = fmaf(c0, h.y, a0.y);
        a0.z = fmaf(c0, h.z, a0.z); a0.w = fmaf(c0, h.w, a0.w);
        a1.x = fmaf(c1, h.x, a1.x); a1.y = fmaf(c1, h.y, a1.y);
        a1.z = fmaf(c1, h.z, a1.z); a1.w = fmaf(c1, h.w, a1.w);
        a2.x = fmaf(c2, h.x, a2.x); a2.y = fmaf(c2, h.y, a2.y);
        a2.z = fmaf(c2, h.z, a2.z); a2.w = fmaf(c2, h.w, a2.w);
        a3.x = fmaf(c3, h.x, a3.x); a3.y = fmaf(c3, h.y, a3.y);
        a3.z = fmaf(c3, h.z, a3.z); a3.w = fmaf(c3, h.w, a3.w);
    }

    float4 bb = sb[lane];
    float4 accs[4] = {a0, a1, a2, a3};
    #pragma unroll
    for (int j = 0; j < 4; j++) {
        int i = ibase + j;
        if (i >= n) break;
        float dij = __shfl_sync(0xffffffffu, __uint_as_float(mypk & ~31u), j);
        float4 acc = accs[j];
        float4 r;
        r.x = dij * fmaxf(fmaf(dij, acc.x, bb.x), 0.f);
        r.y = dij * fmaxf(fmaf(dij, acc.y, bb.y), 0.f);
        r.z = dij * fmaxf(fmaf(dij, acc.z, bb.z), 0.f);
        r.w = dij * fmaxf(fmaf(dij, acc.w, bb.w), 0.f);
        __half2 p0 = __floats2half2_rn(r.x, r.y);
        __half2 p1 = __floats2half2_rn(r.z, r.w);
        uint2 u;
        u.x = *(unsigned int*)&p0;
        u.y = *(unsigned int*)&p1;
        g_y1h[(size_t)i * 32 + lane] = u;
    }
}

__device__ __forceinline__ void acc_row(float4& acc, uint2 u) {
    float2 f0 = __half22float2(*(__half2*)&u.x);
    float2 f1 = __half22float2(*(__half2*)&u.y);
    acc.x += f0.x; acc.y += f0.y; acc.z += f1.x; acc.w += f1.y;
}

// Layer 2 aggregation (fp16 gather, fp32 accum) fused with graph pooling
__global__ void __launch_bounds__(256) k_layer2pool(const int* __restrict__ batch, int n, int E) {
    __shared__ float sy[8 * DIM];
    __shared__ int sg[8];

    int warp = threadIdx.x >> 5, lane = threadIdx.x & 31;
    int i = blockIdx.x * 8 + warp;

    if (i < n) {
        const uint2* y = (const uint2*)g_y1h;
        float di = __uint_as_float(g_ndp[i] & ~31u);
        float4 acc = {0.f, 0.f, 0.f, 0.f};
        acc_row(acc, __ldg(&y[(size_t)i * 32 + lane]));   // self loop

        int e  = g_rowptr[i] + g_bsums[i >> 10];
        int e1 = (i + 1 < n) ? (g_rowptr[i + 1] + g_bsums[(i + 1) >> 10]) : E;

        for (; e + 8 <= e1; e += 8) {
            int s0 = g_edge[e + 0].x, s1 = g_edge[e + 1].x;
            int s2 = g_edge[e + 2].x, s3 = g_edge[e + 3].x;
            int s4 = g_edge[e + 4].x, s5 = g_edge[e + 5].x;
            int s6 = g_edge[e + 6].x, s7 = g_edge[e + 7].x;
            uint2 u0 = __ldg(&y[(size_t)s0 * 32 + lane]);
            uint2 u1 = __ldg(&y[(size_t)s1 * 32 + lane]);
            uint2 u2 = __ldg(&y[(size_t)s2 * 32 + lane]);
            uint2 u3 = __ldg(&y[(size_t)s3 * 32 + lane]);
            uint2 u4 = __ldg(&y[(size_t)s4 * 32 + lane]);
            uint2 u5 = __ldg(&y[(size_t)s5 * 32 + lane]);
            uint2 u6 = __ldg(&y[(size_t)s6 * 32 + lane]);
            uint2 u7 = __ldg(&y[(size_t)s7 * 32 + lane]);
            acc_row(acc, u0); acc_row(acc, u1); acc_row(acc, u2); acc_row(acc, u3);
            acc_row(acc, u4); acc_row(acc, u5); acc_row(acc, u6); acc_row(acc, u7);
        }
        for (; e < e1; e++)
            acc_row(acc, __ldg(&y[(size_t)g_edge[e].x * 32 + lane]));

        acc.x *= di; acc.y *= di; acc.z *= di; acc.w *= di;
        ((float4*)sy)[warp * 32 + lane] = acc;
        if (lane == 0) sg[warp] = batch[i];
    } else {
        if (lane == 0) sg[warp] = -1;
    }
    __syncthreads();

    int f = threadIdx.x;
    if (f < DIM) {
        float run = 0.f; int cg = -1; int cnt = 0;
        #pragma unroll
        for (int r = 0; r < 8; r++) {
            int g = sg[r];
            if (g < 0) continue;
            if (g != cg) {
                if (cg >= 0) {
                    atomicAdd(&g_pool[cg * DIM + f], run);
                    if (f == 0) atomicAdd(&g_gcnt[cg], cnt);
                }
                cg = g; run = 0.f; cnt = 0;
            }
            run += sy[r * DIM + f];
            cnt++;
        }
        if (cg >= 0) {
            atomicAdd(&g_pool[cg * DIM + f], run);
            if (f == 0) atomicAdd(&g_gcnt[cg], cnt);
        }
    }
}

// out[g] = (pool[g]/cnt[g]) @ W2 + b2 ; re-zeros pool/gcnt for next replay
__global__ void k_final(const float* __restrict__ W2, const float* __restrict__ b2,
                        float* __restrict__ out) {
    int g = blockIdx.x, o = threadIdx.x;
    __shared__ float p[DIM];
    int c = g_gcnt[g];
    float inv = (c > 0) ? (1.0f / (float)c) : 0.f;
    p[o] = g_pool[g * DIM + o] * inv;
    g_pool[g * DIM + o] = 0.f;
    if (o == 0) g_gcnt[g] = 0;
    __syncthreads();
    float a0 = 0.f, a1 = 0.f, a2 = 0.f, a3 = 0.f;
    #pragma unroll
    for (int d = 0; d < DIM; d += 4) {
        a0 = fmaf(p[d + 0], W2[(d + 0) * DIM + o], a0);
        a1 = fmaf(p[d + 1], W2[(d + 1) * DIM + o], a1);
        a2 = fmaf(p[d + 2], W2[(d + 2) * DIM + o], a2);
        a3 = fmaf(p[d + 3], W2[(d + 3) * DIM + o], a3);
    }
    out[g * DIM + o] = (c > 0) ? ((a0 + a1) + (a2 + a3) + b2[o]) : 0.f;
}

// ---------------- launcher ----------------
extern "C" void kernel_launch(void* const* d_in, const int* in_sizes, int n_in,
                              void* d_out, int out_size) {
    const int* node_ids = (const int*)d_in[0];
    const int* ei       = (const int*)d_in[1];
    const int* batch    = (const int*)d_in[2];
    int base = (n_in >= 9 && in_sizes[3] == 1) ? 4 : 3;
    const float* emb = (const float*)d_in[base + 0];
    const float* W1  = (const float*)d_in[base + 1];
    const float* b1  = (const float*)d_in[base + 2];
    const float* W2  = (const float*)d_in[base + 3];
    const float* b2  = (const float*)d_in[base + 4];

    int N = in_sizes[0];
    int E = in_sizes[1] / 2;
    int G = out_size / DIM;
    int NB = (N + 1023) / 1024;

    k_hist<<<HTB + (E + 255) / 256, 256>>>(ei, E, emb, W1);
    k_scan1<<<NB, 1024>>>(node_ids, N);
    k_scatter<<<(E + 255) / 256, 256>>>(ei, E);
    k_layer1<<<(N + 31) / 32, 256>>>(b1, N, E);
    k_layer2pool<<<(N + 7) / 8, 256>>>(batch, N, E);
    k_final<<<G, DIM>>>(W2, b2, (float*)d_out);
}